// round 1
// baseline (speedup 1.0000x reference)
#include <cuda_runtime.h>
#include <cuda_bf16.h>
#include <math.h>

#define BB   64
#define SS   512
#define EMB  768
#define HID  512
#define G4   2048      // 4*HID
#define NTAG 9
#define NROW (SS*BB)   // 32768
#define NCOL (2*G4)    // 4096

// ---------------- scratch (static device globals; no allocation) ----------------
__device__ float g_xp  [2u*SS*BB*G4];      // [dir][t][b][g]  512 MB
__device__ float g_hall[2u*SS*BB*HID];     // [dir][t][b][j]  128 MB
__device__ float g_hbuf[2u*2u*BB*HID];     // [buf][dir][b][j]
__device__ float g_emis[SS*BB*NTAG];
__device__ float g_llh [BB];
__device__ float g_msum[BB];
__device__ unsigned g_barcnt;              // zero at load; returns to zero every barrier
__device__ unsigned g_bargen;              // monotone across replays (wrap-safe)

// ---------------- K1: input projection GEMM (fp32, 128x128x16 tiles) ----------------
#define BM 128
#define BN 128
#define BKT 16
#define LDT 132   // padded tile row stride (16B aligned, few conflicts)

__global__ __launch_bounds__(256, 1)
void k1_inproj(const float* __restrict__ x,
               const float* __restrict__ wihf, const float* __restrict__ wihb,
               const float* __restrict__ bf,   const float* __restrict__ bb2)
{
    __shared__ float As[BKT][LDT];
    __shared__ float Bs[BKT][LDT];

    const int tid = threadIdx.x;
    const int tx = tid & 15;          // 16 col groups
    const int ty = tid >> 4;          // 16 row groups
    const int tk = tid & 15;          // loader k
    const int trow = tid >> 4;        // loader row base

    const int m0 = blockIdx.y * BM;
    const int n0 = blockIdx.x * BN;

    float acc[8][8];
#pragma unroll
    for (int i = 0; i < 8; ++i)
#pragma unroll
        for (int j = 0; j < 8; ++j) acc[i][j] = 0.f;

    for (int k0 = 0; k0 < EMB; k0 += BKT) {
#pragma unroll
        for (int r = 0; r < 8; ++r) {
            int m = trow + r * 16;
            int mg = m0 + m;
            int tt = mg >> 6, bb_ = mg & 63;
            As[tk][m] = x[(bb_ * SS + tt) * EMB + k0 + tk];
            int ng = n0 + m;
            float wv = (ng < G4) ? wihf[ng * EMB + k0 + tk]
                                 : wihb[(ng - G4) * EMB + k0 + tk];
            Bs[tk][m] = wv;
        }
        __syncthreads();
#pragma unroll
        for (int k = 0; k < BKT; ++k) {
            float4 a0 = *(const float4*)&As[k][ty * 8];
            float4 a1 = *(const float4*)&As[k][ty * 8 + 4];
            float4 b0 = *(const float4*)&Bs[k][tx * 8];
            float4 b1 = *(const float4*)&Bs[k][tx * 8 + 4];
            float av[8] = {a0.x,a0.y,a0.z,a0.w,a1.x,a1.y,a1.z,a1.w};
            float bv[8] = {b0.x,b0.y,b0.z,b0.w,b1.x,b1.y,b1.z,b1.w};
#pragma unroll
            for (int i = 0; i < 8; ++i)
#pragma unroll
                for (int j = 0; j < 8; ++j) acc[i][j] = fmaf(av[i], bv[j], acc[i][j]);
        }
        __syncthreads();
    }

    // epilogue: + bias, write xp[dir][t][b][g]
    float bias[8];
#pragma unroll
    for (int j = 0; j < 8; ++j) {
        int n = n0 + tx * 8 + j;
        bias[j] = (n < G4) ? bf[n] : bb2[n - G4];
    }
#pragma unroll
    for (int i = 0; i < 8; ++i) {
        int m = m0 + ty * 8 + i;
        int t = m >> 6, b = m & 63;
#pragma unroll
        for (int j = 0; j < 8; ++j) {
            int n = n0 + tx * 8 + j;
            int dir = n >> 11, g = n & 2047;
            g_xp[(((size_t)dir * SS + t) * BB + b) * G4 + g] = acc[i][j] + bias[j];
        }
    }
}

// ---------------- K2: persistent BiLSTM recurrence ----------------
#define NCTA2 128
#define T2    128
#define LDH   513   // padded row stride for h and w tiles

__device__ __forceinline__ float sigf(float v) { return 1.f / (1.f + expf(-v)); }

__device__ __forceinline__ void gridbar()
{
    __syncthreads();
    if (threadIdx.x == 0) {
        unsigned g = *((volatile unsigned*)&g_bargen);
        __threadfence();
        unsigned a = atomicAdd(&g_barcnt, 1u);
        if (a == NCTA2 - 1) {
            g_barcnt = 0;
            __threadfence();
            atomicAdd(&g_bargen, 1u);
        } else {
            while (*((volatile unsigned*)&g_bargen) == g) { __nanosleep(64); }
        }
        __threadfence();
    }
    __syncthreads();
}

__global__ __launch_bounds__(T2, 1)
void k2_lstm(const float* __restrict__ whhf, const float* __restrict__ whhb)
{
    extern __shared__ float smem[];
    float* sw = smem;                 // [32][LDH]
    float* sh = smem + 32 * LDH;      // [64][LDH]
    __shared__ float spre[BB][33];
    __shared__ float sc[BB][9];

    const int dir = blockIdx.x >> 6;
    const int ug  = blockIdx.x & 63;          // unit group: units [ug*8, ug*8+8)
    const float* whh = dir ? whhb : whhf;
    const int tid = threadIdx.x;

    // load weight slice: 32 local gate rows (gate-major: gl = gate*8 + ul)
    for (int i = tid; i < 32 * HID; i += T2) {
        int gl = i >> 9, k = i & 511;
        int gate = gl >> 3, ul = gl & 7;
        int grow = gate * HID + ug * 8 + ul;
        sw[gl * LDH + k] = whh[grow * HID + k];
    }
    for (int i = tid; i < BB * 8; i += T2) sc[i >> 3][i & 7] = 0.f;
    __syncthreads();

    const int bi = tid >> 3;          // 0..15
    const int gi = tid & 7;           // 0..7
    const int b0 = bi * 4;
    const int gl0 = gi * 4;

    for (int s = 0; s < SS; ++s) {
        const int t = dir ? (SS - 1 - s) : s;

        // stage h_prev into SMEM
        if (s == 0) {
            for (int i = tid; i < BB * HID; i += T2)
                sh[(i >> 9) * LDH + (i & 511)] = 0.f;
        } else {
            const float* hsrc = &g_hbuf[((size_t)(s & 1) * 2 + dir) * BB * HID];
            for (int i = tid * 4; i < BB * HID; i += T2 * 4) {
                float4 v = *(const float4*)(hsrc + i);
                float* d = &sh[(i >> 9) * LDH + (i & 511)];
                d[0] = v.x; d[1] = v.y; d[2] = v.z; d[3] = v.w;
            }
        }
        __syncthreads();

        float acc[4][4];
#pragma unroll
        for (int i = 0; i < 4; ++i)
#pragma unroll
            for (int j = 0; j < 4; ++j) acc[i][j] = 0.f;

#pragma unroll 4
        for (int k = 0; k < HID; ++k) {
            float hv[4], wv[4];
#pragma unroll
            for (int i = 0; i < 4; ++i) hv[i] = sh[(b0 + i) * LDH + k];
#pragma unroll
            for (int j = 0; j < 4; ++j) wv[j] = sw[(gl0 + j) * LDH + k];
#pragma unroll
            for (int i = 0; i < 4; ++i)
#pragma unroll
                for (int j = 0; j < 4; ++j) acc[i][j] = fmaf(hv[i], wv[j], acc[i][j]);
        }

        const float* xpb = &g_xp[(((size_t)dir * SS + t) * BB) * G4];
#pragma unroll
        for (int i = 0; i < 4; ++i) {
            int b = b0 + i;
#pragma unroll
            for (int j = 0; j < 4; ++j) {
                int gl = gl0 + j;
                int gate = gl >> 3, ul = gl & 7;
                int grow = gate * HID + ug * 8 + ul;
                spre[b][gl] = acc[i][j] + xpb[(size_t)b * G4 + grow];
            }
        }
        __syncthreads();

        // LSTM cell update: 512 (b, unit) states, 4 per thread
        float* hdst = &g_hbuf[((size_t)((s + 1) & 1) * 2 + dir) * BB * HID];
        float* hall = &g_hall[(((size_t)dir * SS + t) * BB) * HID];
#pragma unroll
        for (int r = 0; r < 4; ++r) {
            int idx = tid * 4 + r;
            int b = idx >> 3, ul = idx & 7;
            float iv = spre[b][0 * 8 + ul];
            float fv = spre[b][1 * 8 + ul];
            float gv = spre[b][2 * 8 + ul];
            float ov = spre[b][3 * 8 + ul];
            float c = sigf(fv) * sc[b][ul] + sigf(iv) * tanhf(gv);
            float h = sigf(ov) * tanhf(c);
            sc[b][ul] = c;
            int j = ug * 8 + ul;
            hdst[(size_t)b * HID + j] = h;
            hall[(size_t)b * HID + j] = h;
        }
        __threadfence();
        gridbar();
    }
}

// ---------------- K3: emissions ----------------
__global__ __launch_bounds__(256, 1)
void k3_emis(const float* __restrict__ wout, const float* __restrict__ bout)
{
    __shared__ float sw[NTAG][2 * HID];   // 36 KB
    for (int i = threadIdx.x; i < NTAG * 2 * HID; i += 256)
        sw[i / (2 * HID)][i % (2 * HID)] = wout[i];
    __syncthreads();

    int warp = blockIdx.x * 8 + (threadIdx.x >> 5);
    int lane = threadIdx.x & 31;
    int t = warp >> 6, b = warp & 63;

    const float* hf = &g_hall[(((size_t)0 * SS + t) * BB + b) * HID];
    const float* hb = &g_hall[(((size_t)1 * SS + t) * BB + b) * HID];

    float acc[NTAG];
#pragma unroll
    for (int q = 0; q < NTAG; ++q) acc[q] = 0.f;

    for (int k = lane; k < HID; k += 32) {
        float h1 = hf[k], h2 = hb[k];
#pragma unroll
        for (int q = 0; q < NTAG; ++q)
            acc[q] = fmaf(h1, sw[q][k], fmaf(h2, sw[q][HID + k], acc[q]));
    }
#pragma unroll
    for (int q = 0; q < NTAG; ++q)
        for (int off = 16; off; off >>= 1)
            acc[q] += __shfl_down_sync(0xffffffffu, acc[q], off);
    if (lane == 0) {
#pragma unroll
        for (int q = 0; q < NTAG; ++q)
            g_emis[((size_t)t * BB + b) * NTAG + q] = acc[q] + bout[q];
    }
}

// ---------------- K4: CRF (num + forward algorithm) ----------------
__global__ __launch_bounds__(1024, 1)
void k4_crf(const int* __restrict__ mask, const int* __restrict__ tags,
            const float* __restrict__ st, const float* __restrict__ et,
            const float* __restrict__ tr)
{
    int w = (blockIdx.x * blockDim.x + threadIdx.x) >> 5;   // 0..63 == batch b
    int lane = threadIdx.x & 31;
    if (w >= BB) return;
    const int b = w;
    const int* mb = mask + b * SS;
    const int* tg = tags + b * SS;

    // numerator (masked transition+emission terms), and mask count
    float numpart = 0.f, mpart = 0.f;
    for (int t = lane; t < SS; t += 32) {
        float m = (float)mb[t];
        mpart += m;
        if (t >= 1)
            numpart += m * (tr[tg[t - 1] * NTAG + tg[t]] +
                            g_emis[((size_t)t * BB + b) * NTAG + tg[t]]);
    }
    for (int off = 16; off; off >>= 1) {
        numpart += __shfl_xor_sync(0xffffffffu, numpart, off);
        mpart   += __shfl_xor_sync(0xffffffffu, mpart, off);
    }

    // forward algorithm: lanes 0..8 hold alpha
    float tc[NTAG];
#pragma unroll
    for (int j = 0; j < NTAG; ++j)
        tc[j] = (lane < NTAG) ? tr[j * NTAG + lane] : 0.f;

    float alpha = (lane < NTAG)
        ? st[lane] + g_emis[((size_t)0 * BB + b) * NTAG + lane]
        : -1e30f;

    for (int t = 1; t < SS; ++t) {
        float e = (lane < NTAG) ? g_emis[((size_t)t * BB + b) * NTAG + lane] : 0.f;
        float v[NTAG];
        float mx = -1e30f;
#pragma unroll
        for (int j = 0; j < NTAG; ++j) {
            v[j] = __shfl_sync(0xffffffffu, alpha, j) + tc[j];
            mx = fmaxf(mx, v[j]);
        }
        float sum = 0.f;
#pragma unroll
        for (int j = 0; j < NTAG; ++j) sum += expf(v[j] - mx);
        float nxt = mx + logf(sum) + e;
        alpha = (mb[t] > 0) ? nxt : alpha;
    }

    // den = logsumexp(alpha + end_trans)
    float vden = (lane < NTAG) ? alpha + et[lane] : -1e30f;
    float mx = vden;
    for (int off = 16; off; off >>= 1) mx = fmaxf(mx, __shfl_xor_sync(0xffffffffu, mx, off));
    float se = (lane < NTAG) ? expf(vden - mx) : 0.f;
    for (int off = 16; off; off >>= 1) se += __shfl_xor_sync(0xffffffffu, se, off);
    float den = mx + logf(se);

    if (lane == 0) {
        int t0 = tg[0];
        float num = numpart + st[t0] + g_emis[((size_t)0 * BB + b) * NTAG + t0];
        int li = (int)(mpart + 0.5f) - 1;
        num += et[tg[li]];
        g_llh[b]  = num - den;
        g_msum[b] = mpart;
    }
}

// ---------------- K5: deterministic final reduce ----------------
__global__ void k5_reduce(float* out)
{
    if (threadIdx.x == 0 && blockIdx.x == 0) {
        float sn = 0.f, sm = 0.f;
        for (int b = 0; b < BB; ++b) { sn += g_llh[b]; sm += g_msum[b]; }
        out[0] = -(sn / sm);
    }
}

// ---------------- launch ----------------
extern "C" void kernel_launch(void* const* d_in, const int* in_sizes, int n_in,
                              void* d_out, int out_size)
{
    const float* x    = (const float*)d_in[0];
    const int*   mask = (const int*)  d_in[1];
    const int*   tags = (const int*)  d_in[2];
    const float* wihf = (const float*)d_in[3];
    const float* whhf = (const float*)d_in[4];
    const float* bf   = (const float*)d_in[5];
    const float* wihb = (const float*)d_in[6];
    const float* whhb = (const float*)d_in[7];
    const float* bb2  = (const float*)d_in[8];
    const float* wout = (const float*)d_in[9];
    const float* bout = (const float*)d_in[10];
    const float* st   = (const float*)d_in[11];
    const float* et   = (const float*)d_in[12];
    const float* tr   = (const float*)d_in[13];
    float* out = (float*)d_out;

    const int smem2 = (32 * LDH + 64 * LDH) * (int)sizeof(float);   // ~197 KB dynamic
    cudaFuncSetAttribute(k2_lstm, cudaFuncAttributeMaxDynamicSharedMemorySize, smem2);

    k1_inproj<<<dim3(NCOL / BN, NROW / BM), 256>>>(x, wihf, wihb, bf, bb2);
    k2_lstm<<<NCTA2, T2, smem2>>>(whhf, whhb);
    k3_emis<<<NROW / 8, 256>>>(wout, bout);
    k4_crf<<<2, 1024>>>(mask, tags, st, et, tr);
    k5_reduce<<<1, 32>>>(out);
}

// round 3
// speedup vs baseline: 1.5700x; 1.5700x over previous
#include <cuda_runtime.h>
#include <cuda_bf16.h>
#include <math.h>
#include <stdint.h>

#define BB   64
#define SS   512
#define EMB  768
#define HID  512
#define G4   2048      // 4*HID
#define NTAG 9
#define NROW (SS*BB)   // 32768
#define NCOL (2*G4)    // 4096

// ---------------- scratch (static device globals; no allocation) ----------------
__device__ float g_xp  [2u*SS*BB*G4];      // [dir][t][b][g]
__device__ float g_hall[2u*SS*BB*HID];     // [dir][t][b][j]
__device__ float g_hbuf[2u*2u*BB*HID];     // [buf][dir][b][j]
__device__ float g_emis[SS*BB*NTAG];
__device__ float g_llh [BB];
__device__ float g_msum[BB];
__device__ unsigned g_barcnt;
__device__ unsigned g_bargen;
__device__ __nv_bfloat16 g_xbf[(size_t)NROW*EMB];   // 48 MB, rows = b*SS+t
__device__ __nv_bfloat16 g_wbf[(size_t)NCOL*EMB];   // 6 MB  (rows 0..2047 fwd, 2048..4095 bwd)

// ======================= helpers =======================
__device__ __forceinline__ uint32_t smem_u32(const void* p) {
    uint32_t a;
    asm("{ .reg .u64 t; cvta.to.shared.u64 t, %1; cvt.u32.u64 %0, t; }" : "=r"(a) : "l"(p));
    return a;
}
__device__ __forceinline__ void cp_async16(uint32_t dst, const void* src) {
    asm volatile("cp.async.cg.shared.global [%0], [%1], 16;" :: "r"(dst), "l"(src) : "memory");
}
__device__ __forceinline__ void cp_commit() {
    asm volatile("cp.async.commit_group;" ::: "memory");
}
__device__ __forceinline__ void cp_wait1() {
    asm volatile("cp.async.wait_group 1;" ::: "memory");
}
__device__ __forceinline__ void cp_wait0() {
    asm volatile("cp.async.wait_group 0;" ::: "memory");
}
__device__ __forceinline__ void ldsm_x4(uint32_t& r0, uint32_t& r1, uint32_t& r2, uint32_t& r3,
                                        uint32_t addr) {
    asm volatile("ldmatrix.sync.aligned.m8n8.x4.shared.b16 {%0,%1,%2,%3}, [%4];"
                 : "=r"(r0), "=r"(r1), "=r"(r2), "=r"(r3) : "r"(addr));
}
__device__ __forceinline__ void mma_bf16(float* c, const uint32_t* a, const uint32_t* b) {
    asm volatile(
        "mma.sync.aligned.m16n8k16.row.col.f32.bf16.bf16.f32 "
        "{%0,%1,%2,%3}, {%4,%5,%6,%7}, {%8,%9}, {%0,%1,%2,%3};"
        : "+f"(c[0]), "+f"(c[1]), "+f"(c[2]), "+f"(c[3])
        : "r"(a[0]), "r"(a[1]), "r"(a[2]), "r"(a[3]), "r"(b[0]), "r"(b[1]));
}

// ---------------- K0: fp32 -> bf16 conversions ----------------
__global__ __launch_bounds__(256, 4) void k0_cvt_x(const float* __restrict__ xf)
{
    size_t n2 = (size_t)NROW * EMB / 2;
    for (size_t i = (size_t)blockIdx.x * 256 + threadIdx.x; i < n2;
         i += (size_t)gridDim.x * 256) {
        float2 v = ((const float2*)xf)[i];
        ((__nv_bfloat162*)g_xbf)[i] = __float22bfloat162_rn(v);
    }
}
__global__ __launch_bounds__(256, 4) void k0_cvt_w(const float* __restrict__ wf,
                                                   const float* __restrict__ wb)
{
    size_t n2 = (size_t)G4 * EMB / 2;
    for (size_t i = (size_t)blockIdx.x * 256 + threadIdx.x; i < n2;
         i += (size_t)gridDim.x * 256) {
        float2 v = ((const float2*)wf)[i];
        ((__nv_bfloat162*)g_wbf)[i] = __float22bfloat162_rn(v);
        float2 u = ((const float2*)wb)[i];
        ((__nv_bfloat162*)g_wbf)[n2 + i] = __float22bfloat162_rn(u);
    }
}

// ---------------- K1: input projection, mma.sync bf16 HMMA ----------------
// CTA tile 128m x 128n, K staged in chunks of 64 bf16. Rows padded to 72 bf16 (144B).
#define KC     64
#define NSTG   (EMB / KC)      // 12
#define LDA    72              // bf16 elements per padded row
#define TILE_BYTES (128 * LDA * 2)   // 18432

__global__ __launch_bounds__(256)
void k1_inproj(const float* __restrict__ bf, const float* __restrict__ bb2)
{
    extern __shared__ __align__(16) char sm1[];
    // layout: Abuf0 | Bbuf0 | Abuf1 | Bbuf1
    uint32_t sbase = smem_u32(sm1);
    __shared__ float sbias[128];

    const int tid  = threadIdx.x;
    const int lane = tid & 31;
    const int wid  = tid >> 5;
    const int m0 = blockIdx.y * 128;
    const int n0 = blockIdx.x * 128;

    if (tid < 128) {
        int n = n0 + tid;
        sbias[tid] = (n < G4) ? bf[n] : bb2[n - G4];
    }

    const __nv_bfloat16* gA = g_xbf + (size_t)m0 * EMB;
    const __nv_bfloat16* gB = g_wbf + (size_t)n0 * EMB;

    // staging: thread handles 4 16B chunks of A and 4 of B per stage
    // chunk q in [0,1024): row = q>>3, cc = q&7  (8 chunks of 16B per 64-elt row)
    const int q0 = tid * 4;

    auto stage = [&](int s, int buf) {
        uint32_t sa = sbase + buf * 2 * TILE_BYTES;
        uint32_t sb = sa + TILE_BYTES;
#pragma unroll
        for (int i = 0; i < 4; ++i) {
            int q = q0 + i;
            int row = q >> 3, cc = q & 7;
            uint32_t off = (uint32_t)row * (LDA * 2) + cc * 16;
            cp_async16(sa + off, gA + (size_t)row * EMB + s * KC + cc * 8);
            cp_async16(sb + off, gB + (size_t)row * EMB + s * KC + cc * 8);
        }
        cp_commit();
    };

    float acc[16][4];
#pragma unroll
    for (int i = 0; i < 16; ++i)
#pragma unroll
        for (int j = 0; j < 4; ++j) acc[i][j] = 0.f;

    const int warp_m = wid >> 2;        // 0..1  -> 64 rows
    const int warp_n = wid & 3;         // 0..3  -> 32 cols
    const int m_w = warp_m * 64;
    const int n_w = warp_n * 32;

    stage(0, 0);

    for (int s = 0; s < NSTG; ++s) {
        int buf = s & 1;
        if (s + 1 < NSTG) { stage(s + 1, buf ^ 1); cp_wait1(); }
        else              { cp_wait0(); }
        __syncthreads();

        uint32_t sa = sbase + buf * 2 * TILE_BYTES;
        uint32_t sb = sa + TILE_BYTES;

#pragma unroll
        for (int kk = 0; kk < KC / 16; ++kk) {
            const int k0 = kk * 16;
            uint32_t af[4][4];
#pragma unroll
            for (int mi = 0; mi < 4; ++mi) {
                uint32_t addr = sa + ((uint32_t)(m_w + mi * 16 + (lane & 15)) * (LDA * 2))
                                   + ((uint32_t)(k0 + (lane >> 4) * 8) * 2);
                ldsm_x4(af[mi][0], af[mi][1], af[mi][2], af[mi][3], addr);
            }
            uint32_t bfrg[4][2];
#pragma unroll
            for (int p = 0; p < 2; ++p) {
                uint32_t nrow = (uint32_t)(n_w + p * 16 + ((lane >> 4) & 1) * 8 + (lane & 7));
                uint32_t kcol = (uint32_t)(k0 + ((lane >> 3) & 1) * 8);
                uint32_t addr = sb + nrow * (LDA * 2) + kcol * 2;
                uint32_t r0, r1, r2, r3;
                ldsm_x4(r0, r1, r2, r3, addr);
                bfrg[p * 2 + 0][0] = r0; bfrg[p * 2 + 0][1] = r1;
                bfrg[p * 2 + 1][0] = r2; bfrg[p * 2 + 1][1] = r3;
            }
#pragma unroll
            for (int mi = 0; mi < 4; ++mi)
#pragma unroll
                for (int ni = 0; ni < 4; ++ni)
                    mma_bf16(acc[mi * 4 + ni], af[mi], bfrg[ni]);
        }
        __syncthreads();
    }

    // epilogue: acc -> g_xp with bias. Thread element (mi,ni): rows m+lane/4 (+8), cols n+2*(lane%4)
#pragma unroll
    for (int mi = 0; mi < 4; ++mi) {
#pragma unroll
        for (int ni = 0; ni < 4; ++ni) {
            int mbase = m0 + m_w + mi * 16 + (lane >> 2);
            int nbase = n0 + n_w + ni * 8 + 2 * (lane & 3);
            int dir = nbase >> 11, g = nbase & 2047;
            float bia0 = sbias[nbase - n0], bia1 = sbias[nbase - n0 + 1];
#pragma unroll
            for (int rr = 0; rr < 2; ++rr) {
                int m = mbase + rr * 8;
                int b = m >> 9, t = m & 511;
                float2 v;
                v.x = acc[mi * 4 + ni][rr * 2 + 0] + bia0;
                v.y = acc[mi * 4 + ni][rr * 2 + 1] + bia1;
                *(float2*)&g_xp[(((size_t)dir * SS + t) * BB + b) * G4 + g] = v;
            }
        }
    }
}

// ---------------- K2: persistent BiLSTM recurrence (vectorized LDS.128) ----------------
#define NCTA2 128
#define T2    128
#define LDH   516   // padded h row stride (16B-aligned float4 rows)
#define LDW   36    // swt row stride (k-major weights)

__device__ __forceinline__ float sigf(float v) { return 1.f / (1.f + expf(-v)); }

__device__ __forceinline__ void gridbar()
{
    __syncthreads();
    if (threadIdx.x == 0) {
        unsigned g = *((volatile unsigned*)&g_bargen);
        __threadfence();
        unsigned a = atomicAdd(&g_barcnt, 1u);
        if (a == NCTA2 - 1) {
            g_barcnt = 0;
            __threadfence();
            atomicAdd(&g_bargen, 1u);
        } else {
            while (*((volatile unsigned*)&g_bargen) == g) { __nanosleep(64); }
        }
        __threadfence();
    }
    __syncthreads();
}

__global__ __launch_bounds__(T2, 1)
void k2_lstm(const float* __restrict__ whhf, const float* __restrict__ whhb)
{
    extern __shared__ float smem[];
    float* swt = smem;                 // [HID][LDW]  k-major: swt[k][gl]
    float* sh  = smem + HID * LDW;     // [64][LDH]
    __shared__ float spre[BB][33];
    __shared__ float sc[BB][9];

    const int dir = blockIdx.x >> 6;
    const int ug  = blockIdx.x & 63;
    const float* whh = dir ? whhb : whhf;
    const int tid = threadIdx.x;

    for (int i = tid; i < 32 * HID; i += T2) {
        int k = i & 511, gl = i >> 9;
        int gate = gl >> 3, ul = gl & 7;
        swt[k * LDW + gl] = whh[(gate * HID + ug * 8 + ul) * HID + k];
    }
    for (int i = tid; i < BB * 8; i += T2) sc[i >> 3][i & 7] = 0.f;
    __syncthreads();

    const int bi = tid >> 3;
    const int gi = tid & 7;
    const int b0 = bi * 4;
    const int gl0 = gi * 4;

    for (int s = 0; s < SS; ++s) {
        const int t = dir ? (SS - 1 - s) : s;

        if (s == 0) {
            for (int i = tid; i < BB * HID; i += T2)
                sh[(i >> 9) * LDH + (i & 511)] = 0.f;
        } else {
            const float* hsrc = &g_hbuf[((size_t)(s & 1) * 2 + dir) * BB * HID];
            for (int i = tid * 4; i < BB * HID; i += T2 * 4) {
                float4 v = *(const float4*)(hsrc + i);
                *(float4*)&sh[(i >> 9) * LDH + (i & 511)] = v;
            }
        }
        __syncthreads();

        float acc[4][4];
#pragma unroll
        for (int i = 0; i < 4; ++i)
#pragma unroll
            for (int j = 0; j < 4; ++j) acc[i][j] = 0.f;

#pragma unroll 2
        for (int k = 0; k < HID; k += 4) {
            float4 h0 = *(const float4*)&sh[(b0 + 0) * LDH + k];
            float4 h1 = *(const float4*)&sh[(b0 + 1) * LDH + k];
            float4 h2 = *(const float4*)&sh[(b0 + 2) * LDH + k];
            float4 h3 = *(const float4*)&sh[(b0 + 3) * LDH + k];
            float4 w0 = *(const float4*)&swt[(k + 0) * LDW + gl0];
            float4 w1 = *(const float4*)&swt[(k + 1) * LDW + gl0];
            float4 w2 = *(const float4*)&swt[(k + 2) * LDW + gl0];
            float4 w3 = *(const float4*)&swt[(k + 3) * LDW + gl0];
#define STEPQ(hq, wq)                                                   \
            acc[0][0] = fmaf(h0.hq, wq.x, acc[0][0]);                   \
            acc[0][1] = fmaf(h0.hq, wq.y, acc[0][1]);                   \
            acc[0][2] = fmaf(h0.hq, wq.z, acc[0][2]);                   \
            acc[0][3] = fmaf(h0.hq, wq.w, acc[0][3]);                   \
            acc[1][0] = fmaf(h1.hq, wq.x, acc[1][0]);                   \
            acc[1][1] = fmaf(h1.hq, wq.y, acc[1][1]);                   \
            acc[1][2] = fmaf(h1.hq, wq.z, acc[1][2]);                   \
            acc[1][3] = fmaf(h1.hq, wq.w, acc[1][3]);                   \
            acc[2][0] = fmaf(h2.hq, wq.x, acc[2][0]);                   \
            acc[2][1] = fmaf(h2.hq, wq.y, acc[2][1]);                   \
            acc[2][2] = fmaf(h2.hq, wq.z, acc[2][2]);                   \
            acc[2][3] = fmaf(h2.hq, wq.w, acc[2][3]);                   \
            acc[3][0] = fmaf(h3.hq, wq.x, acc[3][0]);                   \
            acc[3][1] = fmaf(h3.hq, wq.y, acc[3][1]);                   \
            acc[3][2] = fmaf(h3.hq, wq.z, acc[3][2]);                   \
            acc[3][3] = fmaf(h3.hq, wq.w, acc[3][3]);
            STEPQ(x, w0) STEPQ(y, w1) STEPQ(z, w2) STEPQ(w, w3)
#undef STEPQ
        }

        const float* xpb = &g_xp[(((size_t)dir * SS + t) * BB) * G4];
#pragma unroll
        for (int i = 0; i < 4; ++i) {
            int b = b0 + i;
#pragma unroll
            for (int j = 0; j < 4; ++j) {
                int gl = gl0 + j;
                int gate = gl >> 3, ul = gl & 7;
                int grow = gate * HID + ug * 8 + ul;
                spre[b][gl] = acc[i][j] + xpb[(size_t)b * G4 + grow];
            }
        }
        __syncthreads();

        float* hdst = &g_hbuf[((size_t)((s + 1) & 1) * 2 + dir) * BB * HID];
        float* hall = &g_hall[(((size_t)dir * SS + t) * BB) * HID];
#pragma unroll
        for (int r = 0; r < 4; ++r) {
            int idx = tid * 4 + r;
            int b = idx >> 3, ul = idx & 7;
            float iv = spre[b][0 * 8 + ul];
            float fv = spre[b][1 * 8 + ul];
            float gv = spre[b][2 * 8 + ul];
            float ov = spre[b][3 * 8 + ul];
            float c = sigf(fv) * sc[b][ul] + sigf(iv) * tanhf(gv);
            float h = sigf(ov) * tanhf(c);
            sc[b][ul] = c;
            int j = ug * 8 + ul;
            hdst[(size_t)b * HID + j] = h;
            hall[(size_t)b * HID + j] = h;
        }
        __threadfence();
        gridbar();
    }
}

// ---------------- K3: emissions ----------------
__global__ __launch_bounds__(256, 1)
void k3_emis(const float* __restrict__ wout, const float* __restrict__ bout)
{
    __shared__ float sw[NTAG][2 * HID];
    for (int i = threadIdx.x; i < NTAG * 2 * HID; i += 256)
        sw[i / (2 * HID)][i % (2 * HID)] = wout[i];
    __syncthreads();

    int warp = blockIdx.x * 8 + (threadIdx.x >> 5);
    int lane = threadIdx.x & 31;
    int t = warp >> 6, b = warp & 63;

    const float* hf = &g_hall[(((size_t)0 * SS + t) * BB + b) * HID];
    const float* hb = &g_hall[(((size_t)1 * SS + t) * BB + b) * HID];

    float acc[NTAG];
#pragma unroll
    for (int q = 0; q < NTAG; ++q) acc[q] = 0.f;

    for (int k = lane; k < HID; k += 32) {
        float h1 = hf[k], h2 = hb[k];
#pragma unroll
        for (int q = 0; q < NTAG; ++q)
            acc[q] = fmaf(h1, sw[q][k], fmaf(h2, sw[q][HID + k], acc[q]));
    }
#pragma unroll
    for (int q = 0; q < NTAG; ++q)
        for (int off = 16; off; off >>= 1)
            acc[q] += __shfl_down_sync(0xffffffffu, acc[q], off);
    if (lane == 0) {
#pragma unroll
        for (int q = 0; q < NTAG; ++q)
            g_emis[((size_t)t * BB + b) * NTAG + q] = acc[q] + bout[q];
    }
}

// ---------------- K4: CRF ----------------
__global__ __launch_bounds__(1024, 1)
void k4_crf(const int* __restrict__ mask, const int* __restrict__ tags,
            const float* __restrict__ st, const float* __restrict__ et,
            const float* __restrict__ tr)
{
    int w = (blockIdx.x * blockDim.x + threadIdx.x) >> 5;
    int lane = threadIdx.x & 31;
    if (w >= BB) return;
    const int b = w;
    const int* mb = mask + b * SS;
    const int* tg = tags + b * SS;

    float numpart = 0.f, mpart = 0.f;
    for (int t = lane; t < SS; t += 32) {
        float m = (float)mb[t];
        mpart += m;
        if (t >= 1)
            numpart += m * (tr[tg[t - 1] * NTAG + tg[t]] +
                            g_emis[((size_t)t * BB + b) * NTAG + tg[t]]);
    }
    for (int off = 16; off; off >>= 1) {
        numpart += __shfl_xor_sync(0xffffffffu, numpart, off);
        mpart   += __shfl_xor_sync(0xffffffffu, mpart, off);
    }

    float tc[NTAG];
#pragma unroll
    for (int j = 0; j < NTAG; ++j)
        tc[j] = (lane < NTAG) ? tr[j * NTAG + lane] : 0.f;

    float alpha = (lane < NTAG)
        ? st[lane] + g_emis[((size_t)0 * BB + b) * NTAG + lane]
        : -1e30f;

    for (int t = 1; t < SS; ++t) {
        float e = (lane < NTAG) ? g_emis[((size_t)t * BB + b) * NTAG + lane] : 0.f;
        float v[NTAG];
        float mx = -1e30f;
#pragma unroll
        for (int j = 0; j < NTAG; ++j) {
            v[j] = __shfl_sync(0xffffffffu, alpha, j) + tc[j];
            mx = fmaxf(mx, v[j]);
        }
        float sum = 0.f;
#pragma unroll
        for (int j = 0; j < NTAG; ++j) sum += expf(v[j] - mx);
        float nxt = mx + logf(sum) + e;
        alpha = (mb[t] > 0) ? nxt : alpha;
    }

    float vden = (lane < NTAG) ? alpha + et[lane] : -1e30f;
    float mx = vden;
    for (int off = 16; off; off >>= 1) mx = fmaxf(mx, __shfl_xor_sync(0xffffffffu, mx, off));
    float se = (lane < NTAG) ? expf(vden - mx) : 0.f;
    for (int off = 16; off; off >>= 1) se += __shfl_xor_sync(0xffffffffu, se, off);
    float den = mx + logf(se);

    if (lane == 0) {
        int t0 = tg[0];
        float num = numpart + st[t0] + g_emis[((size_t)0 * BB + b) * NTAG + t0];
        int li = (int)(mpart + 0.5f) - 1;
        num += et[tg[li]];
        g_llh[b]  = num - den;
        g_msum[b] = mpart;
    }
}

// ---------------- K5: deterministic final reduce ----------------
__global__ void k5_reduce(float* out)
{
    if (threadIdx.x == 0 && blockIdx.x == 0) {
        float sn = 0.f, sm = 0.f;
        for (int b = 0; b < BB; ++b) { sn += g_llh[b]; sm += g_msum[b]; }
        out[0] = -(sn / sm);
    }
}

// ---------------- launch ----------------
extern "C" void kernel_launch(void* const* d_in, const int* in_sizes, int n_in,
                              void* d_out, int out_size)
{
    const float* x    = (const float*)d_in[0];
    const int*   mask = (const int*)  d_in[1];
    const int*   tags = (const int*)  d_in[2];
    const float* wihf = (const float*)d_in[3];
    const float* whhf = (const float*)d_in[4];
    const float* bf   = (const float*)d_in[5];
    const float* wihb = (const float*)d_in[6];
    const float* whhb = (const float*)d_in[7];
    const float* bb2  = (const float*)d_in[8];
    const float* wout = (const float*)d_in[9];
    const float* bout = (const float*)d_in[10];
    const float* st   = (const float*)d_in[11];
    const float* et   = (const float*)d_in[12];
    const float* tr   = (const float*)d_in[13];
    float* out = (float*)d_out;

    const int smem1 = 4 * TILE_BYTES;   // 73728B: A0 B0 A1 B1
    const int smem2 = (HID * LDW + 64 * LDH) * (int)sizeof(float);
    static int inited = 0;
    if (!inited) {
        cudaFuncSetAttribute(k1_inproj, cudaFuncAttributeMaxDynamicSharedMemorySize, smem1);
        cudaFuncSetAttribute(k2_lstm, cudaFuncAttributeMaxDynamicSharedMemorySize, smem2);
        inited = 1;
    }

    k0_cvt_x<<<2048, 256>>>(x);
    k0_cvt_w<<<512, 256>>>(wihf, wihb);
    k1_inproj<<<dim3(NCOL / 128, NROW / 128), 256, smem1>>>(bf, bb2);
    k2_lstm<<<NCTA2, T2, smem2>>>(whhf, whhb);
    k3_emis<<<NROW / 8, 256>>>(wout, bout);
    k4_crf<<<2, 1024>>>(mask, tags, st, et, tr);
    k5_reduce<<<1, 32>>>(out);
}

// round 4
// speedup vs baseline: 3.4683x; 2.2090x over previous
#include <cuda_runtime.h>
#include <cuda_bf16.h>
#include <math.h>
#include <stdint.h>

#define BB   64
#define SS   512
#define EMB  768
#define HID  512
#define G4   2048      // 4*HID
#define NTAG 9
#define NROW (SS*BB)   // 32768
#define NCOL (2*G4)    // 4096

// ---------------- scratch (static device globals; no allocation) ----------------
__device__ float g_xp  [2u*SS*BB*G4];      // [dir][t][b][g]
__device__ float g_emis[SS*BB*NTAG];
__device__ float g_llh [BB];
__device__ float g_msum[BB];
__device__ unsigned g_barcnt2[2];
__device__ unsigned g_bargen2[2];
__device__ __nv_bfloat16 g_xbf  [(size_t)NROW*EMB];     // 48 MB, rows = b*SS+t
__device__ __nv_bfloat16 g_wbf  [(size_t)NCOL*EMB];     // 6 MB
__device__ __nv_bfloat16 g_whhbf[2u*G4*HID];            // 8 MB [dir][row][k]
__device__ __nv_bfloat16 g_hbf  [2u*2u*BB*HID];         // [buf][dir][b][j]
__device__ __nv_bfloat16 g_hallbf[2u*SS*BB*HID];        // 64 MB [dir][t][b][j]

// ======================= helpers =======================
__device__ __forceinline__ uint32_t smem_u32(const void* p) {
    uint32_t a;
    asm("{ .reg .u64 t; cvta.to.shared.u64 t, %1; cvt.u32.u64 %0, t; }" : "=r"(a) : "l"(p));
    return a;
}
__device__ __forceinline__ void cp_async16(uint32_t dst, const void* src) {
    asm volatile("cp.async.cg.shared.global [%0], [%1], 16;" :: "r"(dst), "l"(src) : "memory");
}
__device__ __forceinline__ void cp_commit() {
    asm volatile("cp.async.commit_group;" ::: "memory");
}
__device__ __forceinline__ void cp_wait1() {
    asm volatile("cp.async.wait_group 1;" ::: "memory");
}
__device__ __forceinline__ void cp_wait0() {
    asm volatile("cp.async.wait_group 0;" ::: "memory");
}
__device__ __forceinline__ void ldsm_x4(uint32_t& r0, uint32_t& r1, uint32_t& r2, uint32_t& r3,
                                        uint32_t addr) {
    asm volatile("ldmatrix.sync.aligned.m8n8.x4.shared.b16 {%0,%1,%2,%3}, [%4];"
                 : "=r"(r0), "=r"(r1), "=r"(r2), "=r"(r3) : "r"(addr));
}
__device__ __forceinline__ void mma_bf16(float* c, const uint32_t* a, const uint32_t* b) {
    asm volatile(
        "mma.sync.aligned.m16n8k16.row.col.f32.bf16.bf16.f32 "
        "{%0,%1,%2,%3}, {%4,%5,%6,%7}, {%8,%9}, {%0,%1,%2,%3};"
        : "+f"(c[0]), "+f"(c[1]), "+f"(c[2]), "+f"(c[3])
        : "r"(a[0]), "r"(a[1]), "r"(a[2]), "r"(a[3]), "r"(b[0]), "r"(b[1]));
}
__device__ __forceinline__ float sigf(float v) { return 1.f / (1.f + expf(-v)); }

// ---------------- K0: fp32 -> bf16 conversions ----------------
__global__ __launch_bounds__(256, 4) void k0_cvt_x(const float* __restrict__ xf)
{
    size_t n2 = (size_t)NROW * EMB / 2;
    for (size_t i = (size_t)blockIdx.x * 256 + threadIdx.x; i < n2;
         i += (size_t)gridDim.x * 256) {
        float2 v = ((const float2*)xf)[i];
        ((__nv_bfloat162*)g_xbf)[i] = __float22bfloat162_rn(v);
    }
}
__global__ __launch_bounds__(256, 4) void k0_cvt_w(const float* __restrict__ wf,
                                                   const float* __restrict__ wb)
{
    size_t n2 = (size_t)G4 * EMB / 2;
    for (size_t i = (size_t)blockIdx.x * 256 + threadIdx.x; i < n2;
         i += (size_t)gridDim.x * 256) {
        float2 v = ((const float2*)wf)[i];
        ((__nv_bfloat162*)g_wbf)[i] = __float22bfloat162_rn(v);
        float2 u = ((const float2*)wb)[i];
        ((__nv_bfloat162*)g_wbf)[n2 + i] = __float22bfloat162_rn(u);
    }
}
__global__ __launch_bounds__(256, 4) void k0_cvt_whh(const float* __restrict__ wf,
                                                     const float* __restrict__ wb)
{
    size_t n2 = (size_t)G4 * HID / 2;
    for (size_t i = (size_t)blockIdx.x * 256 + threadIdx.x; i < n2;
         i += (size_t)gridDim.x * 256) {
        float2 v = ((const float2*)wf)[i];
        ((__nv_bfloat162*)g_whhbf)[i] = __float22bfloat162_rn(v);
        float2 u = ((const float2*)wb)[i];
        ((__nv_bfloat162*)g_whhbf)[n2 + i] = __float22bfloat162_rn(u);
    }
}

// ---------------- K1: input projection, mma.sync bf16 HMMA ----------------
#define KC     64
#define NSTG   (EMB / KC)      // 12
#define LDA    72              // bf16 elements per padded row
#define TILE_BYTES (128 * LDA * 2)   // 18432

__global__ __launch_bounds__(256)
void k1_inproj(const float* __restrict__ bf, const float* __restrict__ bb2)
{
    extern __shared__ __align__(16) char sm1[];
    uint32_t sbase = smem_u32(sm1);
    __shared__ float sbias[128];

    const int tid  = threadIdx.x;
    const int lane = tid & 31;
    const int wid  = tid >> 5;
    const int m0 = blockIdx.y * 128;
    const int n0 = blockIdx.x * 128;

    if (tid < 128) {
        int n = n0 + tid;
        sbias[tid] = (n < G4) ? bf[n] : bb2[n - G4];
    }

    const __nv_bfloat16* gA = g_xbf + (size_t)m0 * EMB;
    const __nv_bfloat16* gB = g_wbf + (size_t)n0 * EMB;
    const int q0 = tid * 4;

    auto stage = [&](int s, int buf) {
        uint32_t sa = sbase + buf * 2 * TILE_BYTES;
        uint32_t sb = sa + TILE_BYTES;
#pragma unroll
        for (int i = 0; i < 4; ++i) {
            int q = q0 + i;
            int row = q >> 3, cc = q & 7;
            uint32_t off = (uint32_t)row * (LDA * 2) + cc * 16;
            cp_async16(sa + off, gA + (size_t)row * EMB + s * KC + cc * 8);
            cp_async16(sb + off, gB + (size_t)row * EMB + s * KC + cc * 8);
        }
        cp_commit();
    };

    float acc[16][4];
#pragma unroll
    for (int i = 0; i < 16; ++i)
#pragma unroll
        for (int j = 0; j < 4; ++j) acc[i][j] = 0.f;

    const int warp_m = wid >> 2;
    const int warp_n = wid & 3;
    const int m_w = warp_m * 64;
    const int n_w = warp_n * 32;

    stage(0, 0);

    for (int s = 0; s < NSTG; ++s) {
        int buf = s & 1;
        if (s + 1 < NSTG) { stage(s + 1, buf ^ 1); cp_wait1(); }
        else              { cp_wait0(); }
        __syncthreads();

        uint32_t sa = sbase + buf * 2 * TILE_BYTES;
        uint32_t sb = sa + TILE_BYTES;

#pragma unroll
        for (int kk = 0; kk < KC / 16; ++kk) {
            const int k0 = kk * 16;
            uint32_t af[4][4];
#pragma unroll
            for (int mi = 0; mi < 4; ++mi) {
                uint32_t addr = sa + ((uint32_t)(m_w + mi * 16 + (lane & 15)) * (LDA * 2))
                                   + ((uint32_t)(k0 + (lane >> 4) * 8) * 2);
                ldsm_x4(af[mi][0], af[mi][1], af[mi][2], af[mi][3], addr);
            }
            uint32_t bfrg[4][2];
#pragma unroll
            for (int p = 0; p < 2; ++p) {
                uint32_t nrow = (uint32_t)(n_w + p * 16 + ((lane >> 4) & 1) * 8 + (lane & 7));
                uint32_t kcol = (uint32_t)(k0 + ((lane >> 3) & 1) * 8);
                uint32_t addr = sb + nrow * (LDA * 2) + kcol * 2;
                uint32_t r0, r1, r2, r3;
                ldsm_x4(r0, r1, r2, r3, addr);
                bfrg[p * 2 + 0][0] = r0; bfrg[p * 2 + 0][1] = r1;
                bfrg[p * 2 + 1][0] = r2; bfrg[p * 2 + 1][1] = r3;
            }
#pragma unroll
            for (int mi = 0; mi < 4; ++mi)
#pragma unroll
                for (int ni = 0; ni < 4; ++ni)
                    mma_bf16(acc[mi * 4 + ni], af[mi], bfrg[ni]);
        }
        __syncthreads();
    }

#pragma unroll
    for (int mi = 0; mi < 4; ++mi) {
#pragma unroll
        for (int ni = 0; ni < 4; ++ni) {
            int mbase = m0 + m_w + mi * 16 + (lane >> 2);
            int nbase = n0 + n_w + ni * 8 + 2 * (lane & 3);
            int dir = nbase >> 11, g = nbase & 2047;
            float bia0 = sbias[nbase - n0], bia1 = sbias[nbase - n0 + 1];
#pragma unroll
            for (int rr = 0; rr < 2; ++rr) {
                int m = mbase + rr * 8;
                int b = m >> 9, t = m & 511;
                float2 v;
                v.x = acc[mi * 4 + ni][rr * 2 + 0] + bia0;
                v.y = acc[mi * 4 + ni][rr * 2 + 1] + bia1;
                *(float2*)&g_xp[(((size_t)dir * SS + t) * BB + b) * G4 + g] = v;
            }
        }
    }
}

// ---------------- K2: persistent BiLSTM recurrence (HMMA, register-resident cell state) ----------------
#define LDB 520    // bf16 per padded SMEM row (1040B, 16B-aligned, ldmatrix conflict-free)

__device__ __forceinline__ void gridbar2(int dir)
{
    __syncthreads();
    if (threadIdx.x == 0) {
        unsigned g = *((volatile unsigned*)&g_bargen2[dir]);
        __threadfence();
        unsigned a = atomicAdd(&g_barcnt2[dir], 1u);
        if (a == 63u) {
            g_barcnt2[dir] = 0;
            __threadfence();
            atomicAdd(&g_bargen2[dir], 1u);
        } else {
            while (*((volatile unsigned*)&g_bargen2[dir]) == g) { __nanosleep(32); }
        }
        __threadfence();
    }
    __syncthreads();
}

__global__ __launch_bounds__(128, 1)
void k2_lstm_tc()
{
    extern __shared__ __align__(16) char sm2[];
    __nv_bfloat16* swb = (__nv_bfloat16*)sm2;      // [32][LDB] weights (persistent)
    __nv_bfloat16* shb = swb + 32 * LDB;           // [64][LDB] h tile
    const uint32_t sw_u = smem_u32(swb);
    const uint32_t sh_u = smem_u32(shb);

    const int dir = blockIdx.x >> 6;
    const int ug  = blockIdx.x & 63;
    const int tid = threadIdx.x, lane = tid & 31, wid = tid >> 5;

    // load this CTA's 32 gate rows (gl = gate*8 + ul), k-major
    const __nv_bfloat16* wsrc = g_whhbf + (size_t)dir * G4 * HID;
    for (int i = tid; i < 32 * (HID / 8); i += 128) {
        int gl = i >> 6, cc = i & 63;
        int grow = (gl >> 3) * HID + ug * 8 + (gl & 7);
        *(uint4*)&swb[gl * LDB + cc * 8] = *(const uint4*)&wsrc[(size_t)grow * HID + cc * 8];
    }
    __syncthreads();

    float creg[4] = {0.f, 0.f, 0.f, 0.f};          // cell state, [r*2+e], register-resident
    const int brow = wid * 16 + (lane >> 2);       // batch row (+0 / +8)
    const int ul0  = 2 * (lane & 3);               // unit pair within group
    const int jcol = ug * 8 + ul0;                 // global hidden index (even)

    for (int s = 0; s < SS; ++s) {
        const int t = dir ? (SS - 1 - s) : s;
        float acc[4][4];                            // [gate][r*2+e]
#pragma unroll
        for (int a = 0; a < 4; ++a)
#pragma unroll
            for (int bq = 0; bq < 4; ++bq) acc[a][bq] = 0.f;

        if (s > 0) {
            // stage h_prev (64x512 bf16) into SMEM
            const __nv_bfloat16* hsrc = g_hbf + ((size_t)(s & 1) * 2 + dir) * BB * HID;
#pragma unroll
            for (int i = 0; i < 32; ++i) {
                int q = i * 128 + tid;
                int row = q >> 6, cc = q & 63;
                cp_async16(sh_u + (uint32_t)row * (LDB * 2) + (uint32_t)cc * 16,
                           hsrc + (size_t)row * HID + cc * 8);
            }
            cp_commit();
            cp_wait0();
            __syncthreads();

#pragma unroll
            for (int kk = 0; kk < HID / 16; ++kk) {
                const int k0 = kk * 16;
                uint32_t af[4];
                {
                    uint32_t addr = sh_u + (uint32_t)(wid * 16 + (lane & 15)) * (LDB * 2)
                                         + (uint32_t)(k0 + (lane >> 4) * 8) * 2;
                    ldsm_x4(af[0], af[1], af[2], af[3], addr);
                }
                uint32_t bfrg[4][2];
#pragma unroll
                for (int p = 0; p < 2; ++p) {
                    uint32_t nrow = (uint32_t)(p * 16 + ((lane >> 4) & 1) * 8 + (lane & 7));
                    uint32_t kcol = (uint32_t)(k0 + ((lane >> 3) & 1) * 8);
                    uint32_t addr = sw_u + nrow * (LDB * 2) + kcol * 2;
                    uint32_t r0, r1, r2, r3;
                    ldsm_x4(r0, r1, r2, r3, addr);
                    bfrg[p * 2 + 0][0] = r0; bfrg[p * 2 + 0][1] = r1;
                    bfrg[p * 2 + 1][0] = r2; bfrg[p * 2 + 1][1] = r3;
                }
#pragma unroll
                for (int ni = 0; ni < 4; ++ni) mma_bf16(acc[ni], af, bfrg[ni]);
            }
        }

        // add xp (fp32), fully register-local cell update
        const float* xpb = g_xp + (((size_t)dir * SS + t) * BB) * G4;
#pragma unroll
        for (int r = 0; r < 2; ++r) {
            int b = brow + r * 8;
#pragma unroll
            for (int gate = 0; gate < 4; ++gate) {
                float2 xv = *(const float2*)&xpb[(size_t)b * G4 + gate * HID + jcol];
                acc[gate][r * 2 + 0] += xv.x;
                acc[gate][r * 2 + 1] += xv.y;
            }
        }

        __nv_bfloat16* hdst = g_hbf + ((size_t)((s + 1) & 1) * 2 + dir) * BB * HID;
        __nv_bfloat16* hall = g_hallbf + ((size_t)dir * SS + t) * BB * HID;
#pragma unroll
        for (int r = 0; r < 2; ++r) {
            int b = brow + r * 8;
            float hv[2];
#pragma unroll
            for (int e = 0; e < 2; ++e) {
                int q = r * 2 + e;
                float i_ = sigf(acc[0][q]);
                float f_ = sigf(acc[1][q]);
                float g_ = tanhf(acc[2][q]);
                float o_ = sigf(acc[3][q]);
                float c = f_ * creg[q] + i_ * g_;
                creg[q] = c;
                hv[e] = o_ * tanhf(c);
            }
            __nv_bfloat162 hb2 = __floats2bfloat162_rn(hv[0], hv[1]);
            *(__nv_bfloat162*)&hdst[(size_t)b * HID + jcol] = hb2;
            *(__nv_bfloat162*)&hall[(size_t)b * HID + jcol] = hb2;
        }
        __threadfence();
        gridbar2(dir);
    }
}

// ---------------- K3: emissions (bf16 h) ----------------
__global__ __launch_bounds__(256, 1)
void k3_emis(const float* __restrict__ wout, const float* __restrict__ bout)
{
    __shared__ float sw[NTAG][2 * HID];
    for (int i = threadIdx.x; i < NTAG * 2 * HID; i += 256)
        sw[i / (2 * HID)][i % (2 * HID)] = wout[i];
    __syncthreads();

    int warp = blockIdx.x * 8 + (threadIdx.x >> 5);
    int lane = threadIdx.x & 31;
    int t = warp >> 6, b = warp & 63;

    const __nv_bfloat16* hf = g_hallbf + (((size_t)0 * SS + t) * BB + b) * HID;
    const __nv_bfloat16* hb = g_hallbf + (((size_t)1 * SS + t) * BB + b) * HID;

    float acc[NTAG];
#pragma unroll
    for (int q = 0; q < NTAG; ++q) acc[q] = 0.f;

    for (int k2 = lane; k2 < HID / 2; k2 += 32) {
        __nv_bfloat162 a2 = *(const __nv_bfloat162*)&hf[2 * k2];
        __nv_bfloat162 c2 = *(const __nv_bfloat162*)&hb[2 * k2];
        float f0 = __bfloat162float(a2.x), f1 = __bfloat162float(a2.y);
        float g0 = __bfloat162float(c2.x), g1 = __bfloat162float(c2.y);
#pragma unroll
        for (int q = 0; q < NTAG; ++q) {
            acc[q] = fmaf(f0, sw[q][2 * k2], acc[q]);
            acc[q] = fmaf(f1, sw[q][2 * k2 + 1], acc[q]);
            acc[q] = fmaf(g0, sw[q][HID + 2 * k2], acc[q]);
            acc[q] = fmaf(g1, sw[q][HID + 2 * k2 + 1], acc[q]);
        }
    }
#pragma unroll
    for (int q = 0; q < NTAG; ++q)
        for (int off = 16; off; off >>= 1)
            acc[q] += __shfl_down_sync(0xffffffffu, acc[q], off);
    if (lane == 0) {
#pragma unroll
        for (int q = 0; q < NTAG; ++q)
            g_emis[((size_t)t * BB + b) * NTAG + q] = acc[q] + bout[q];
    }
}

// ---------------- K4: CRF ----------------
__global__ __launch_bounds__(1024, 1)
void k4_crf(const int* __restrict__ mask, const int* __restrict__ tags,
            const float* __restrict__ st, const float* __restrict__ et,
            const float* __restrict__ tr)
{
    int w = (blockIdx.x * blockDim.x + threadIdx.x) >> 5;
    int lane = threadIdx.x & 31;
    if (w >= BB) return;
    const int b = w;
    const int* mb = mask + b * SS;
    const int* tg = tags + b * SS;

    float numpart = 0.f, mpart = 0.f;
    for (int t = lane; t < SS; t += 32) {
        float m = (float)mb[t];
        mpart += m;
        if (t >= 1)
            numpart += m * (tr[tg[t - 1] * NTAG + tg[t]] +
                            g_emis[((size_t)t * BB + b) * NTAG + tg[t]]);
    }
    for (int off = 16; off; off >>= 1) {
        numpart += __shfl_xor_sync(0xffffffffu, numpart, off);
        mpart   += __shfl_xor_sync(0xffffffffu, mpart, off);
    }

    float tc[NTAG];
#pragma unroll
    for (int j = 0; j < NTAG; ++j)
        tc[j] = (lane < NTAG) ? tr[j * NTAG + lane] : 0.f;

    float alpha = (lane < NTAG)
        ? st[lane] + g_emis[((size_t)0 * BB + b) * NTAG + lane]
        : -1e30f;

    for (int t = 1; t < SS; ++t) {
        float e = (lane < NTAG) ? g_emis[((size_t)t * BB + b) * NTAG + lane] : 0.f;
        float v[NTAG];
        float mx = -1e30f;
#pragma unroll
        for (int j = 0; j < NTAG; ++j) {
            v[j] = __shfl_sync(0xffffffffu, alpha, j) + tc[j];
            mx = fmaxf(mx, v[j]);
        }
        float sum = 0.f;
#pragma unroll
        for (int j = 0; j < NTAG; ++j) sum += expf(v[j] - mx);
        float nxt = mx + logf(sum) + e;
        alpha = (mb[t] > 0) ? nxt : alpha;
    }

    float vden = (lane < NTAG) ? alpha + et[lane] : -1e30f;
    float mx = vden;
    for (int off = 16; off; off >>= 1) mx = fmaxf(mx, __shfl_xor_sync(0xffffffffu, mx, off));
    float se = (lane < NTAG) ? expf(vden - mx) : 0.f;
    for (int off = 16; off; off >>= 1) se += __shfl_xor_sync(0xffffffffu, se, off);
    float den = mx + logf(se);

    if (lane == 0) {
        int t0 = tg[0];
        float num = numpart + st[t0] + g_emis[((size_t)0 * BB + b) * NTAG + t0];
        int li = (int)(mpart + 0.5f) - 1;
        num += et[tg[li]];
        g_llh[b]  = num - den;
        g_msum[b] = mpart;
    }
}

// ---------------- K5: deterministic final reduce ----------------
__global__ void k5_reduce(float* out)
{
    if (threadIdx.x == 0 && blockIdx.x == 0) {
        float sn = 0.f, sm = 0.f;
        for (int b = 0; b < BB; ++b) { sn += g_llh[b]; sm += g_msum[b]; }
        out[0] = -(sn / sm);
    }
}

// ---------------- launch ----------------
extern "C" void kernel_launch(void* const* d_in, const int* in_sizes, int n_in,
                              void* d_out, int out_size)
{
    const float* x    = (const float*)d_in[0];
    const int*   mask = (const int*)  d_in[1];
    const int*   tags = (const int*)  d_in[2];
    const float* wihf = (const float*)d_in[3];
    const float* whhf = (const float*)d_in[4];
    const float* bf   = (const float*)d_in[5];
    const float* wihb = (const float*)d_in[6];
    const float* whhb = (const float*)d_in[7];
    const float* bb2  = (const float*)d_in[8];
    const float* wout = (const float*)d_in[9];
    const float* bout = (const float*)d_in[10];
    const float* st   = (const float*)d_in[11];
    const float* et   = (const float*)d_in[12];
    const float* tr   = (const float*)d_in[13];
    float* out = (float*)d_out;

    const int smem1 = 4 * TILE_BYTES;                       // 73728
    const int smem2 = 96 * LDB * (int)sizeof(__nv_bfloat16); // 99840
    static int inited = 0;
    if (!inited) {
        cudaFuncSetAttribute(k1_inproj, cudaFuncAttributeMaxDynamicSharedMemorySize, smem1);
        cudaFuncSetAttribute(k2_lstm_tc, cudaFuncAttributeMaxDynamicSharedMemorySize, smem2);
        inited = 1;
    }

    k0_cvt_x<<<2048, 256>>>(x);
    k0_cvt_w<<<512, 256>>>(wihf, wihb);
    k0_cvt_whh<<<512, 256>>>(whhf, whhb);
    k1_inproj<<<dim3(NCOL / 128, NROW / 128), 256, smem1>>>(bf, bb2);
    k2_lstm_tc<<<128, 128, smem2>>>();
    k3_emis<<<NROW / 8, 256>>>(wout, bout);
    k4_crf<<<2, 1024>>>(mask, tags, st, et, tr);
    k5_reduce<<<1, 32>>>(out);
}